// round 14
// baseline (speedup 1.0000x reference)
#include <cuda_runtime.h>
#include <cuda_bf16.h>
#include <math.h>
#include <stdint.h>

// ---------------- problem constants ----------------
#define N_IMG   16384           // B * 2 * NB_DIGITS
#define NPAIR   (N_IMG / 2)
#define NBATCH  4096
#define SUMS    199

typedef unsigned long long ull;

// ---------------- f32x2 packed helpers ----------------
__device__ __forceinline__ ull ffma2(ull a, ull b, ull c) {
    ull d;
    asm("fma.rn.f32x2 %0, %1, %2, %3;" : "=l"(d) : "l"(a), "l"(b), "l"(c));
    return d;
}
__device__ __forceinline__ ull pack2(float lo, float hi) {
    ull r;
    asm("mov.b64 %0, {%1, %2};" : "=l"(r) : "f"(lo), "f"(hi));
    return r;
}
__device__ __forceinline__ float2 unpack2(ull v) {
    float2 f;
    asm("mov.b64 {%0, %1}, %2;" : "=f"(f.x), "=f"(f.y) : "l"(v));
    return f;
}

// ---------------- mma.sync helpers (bf16 HMMA) ----------------
#define MMA_BF16(c, a0, a1, a2, a3, b0, b1) \
    asm volatile("mma.sync.aligned.m16n8k16.row.col.f32.bf16.bf16.f32 " \
        "{%0,%1,%2,%3}, {%4,%5,%6,%7}, {%8,%9}, {%0,%1,%2,%3};" \
        : "+f"((c)[0]), "+f"((c)[1]), "+f"((c)[2]), "+f"((c)[3]) \
        : "r"(a0), "r"(a1), "r"(a2), "r"(a3), "r"(b0), "r"(b1))

__device__ __forceinline__ uint32_t pkbf(float x, float y) {
    __nv_bfloat162 v = __floats2bfloat162_rn(x, y);   // lo=x, hi=y
    return *(uint32_t*)&v;
}
__device__ __forceinline__ uint32_t pkbf16(__nv_bfloat16 lo, __nv_bfloat16 hi) {
    return ((uint32_t)__bfloat16_as_ushort(hi) << 16) | (uint32_t)__bfloat16_as_ushort(lo);
}

// ---------------- device scratch ----------------
__device__ ull    g_pool1p[(size_t)NPAIR * 864];  // conv1+pool+relu, pair-packed
__device__ float  g_pool2f[(size_t)N_IMG * 256];  // conv2+pool+relu, per-image NCHW
__device__ float  g_logp [(size_t)N_IMG * 10];    // per-image log-softmax
__device__ float  g_w3t[84 * 10];                 // fc3 w transposed [k][j]
// fc weights in mma B-fragment layout (hi/lo bf16 split)
__device__ uint2  g_B1fh[16 * 16 * 32];
__device__ uint2  g_B1fl[16 * 16 * 32];
__device__ uint2  g_B2fh[8 * 11 * 32];
__device__ uint2  g_B2fl[8 * 11 * 32];
// conv2 weights in mma A-fragment layout: [ks 10][lane 32], hi/lo
__device__ uint4  g_CAh[10 * 32];
__device__ uint4  g_CAl[10 * 32];

// ---------------- weight prep ----------------
__global__ void prep_kernel(const float* __restrict__ c2w,
                            const float* __restrict__ w1, const float* __restrict__ w2,
                            const float* __restrict__ w3) {
    int i = blockIdx.x * blockDim.x + threadIdx.x;
    if (i < 8192) {                       // B1 frags: 16 ks x 16 nt x 32 lanes
        int lane = i & 31, nt = (i >> 5) & 15, ks = i >> 9;
        int n = nt * 8 + (lane >> 2);
        int k0 = ks * 16 + (lane & 3) * 2;
        float e[4];
        #pragma unroll
        for (int q = 0; q < 4; q++) {
            int k = k0 + (q >> 1) * 8 + (q & 1);
            e[q] = (n < 120) ? w1[n * 256 + k] : 0.f;
        }
        __nv_bfloat16 h[4]; float l[4];
        #pragma unroll
        for (int q = 0; q < 4; q++) { h[q] = __float2bfloat16(e[q]); l[q] = e[q] - __bfloat162float(h[q]); }
        g_B1fh[i] = make_uint2(pkbf16(h[0], h[1]), pkbf16(h[2], h[3]));
        g_B1fl[i] = make_uint2(pkbf(l[0], l[1]), pkbf(l[2], l[3]));
    } else if (i < 8192 + 2816) {         // B2 frags: 8 ks x 11 nt x 32 lanes
        int r = i - 8192;
        int lane = r & 31, nt = (r >> 5) % 11, ks = r / 352;
        int n = nt * 8 + (lane >> 2);
        int k0 = ks * 16 + (lane & 3) * 2;
        float e[4];
        #pragma unroll
        for (int q = 0; q < 4; q++) {
            int k = k0 + (q >> 1) * 8 + (q & 1);
            e[q] = (n < 84 && k < 120) ? w2[n * 120 + k] : 0.f;
        }
        __nv_bfloat16 h[4]; float l[4];
        #pragma unroll
        for (int q = 0; q < 4; q++) { h[q] = __float2bfloat16(e[q]); l[q] = e[q] - __bfloat162float(h[q]); }
        g_B2fh[r] = make_uint2(pkbf16(h[0], h[1]), pkbf16(h[2], h[3]));
        g_B2fl[r] = make_uint2(pkbf(l[0], l[1]), pkbf(l[2], l[3]));
    }
    if (i < 320) {                        // conv2 A frags: 10 ks x 32 lanes
        int lane = i & 31, ks = i >> 5;
        int g2 = lane >> 2, tg = lane & 3;
        int k0 = ks * 16 + tg * 2;
        float e[8];
        #pragma unroll
        for (int q = 0; q < 8; q++) {
            int row = g2 + ((q >> 1) & 1) * 8;         // a0:g a1:g+8 a2:g a3:g+8
            int k = k0 + (q & 1) + (q >> 2) * 8;       // pairs at k0 and k0+8
            e[q] = (k < 150) ? c2w[row * 150 + k] : 0.f;
        }
        __nv_bfloat16 h[8]; float l[8];
        #pragma unroll
        for (int q = 0; q < 8; q++) { h[q] = __float2bfloat16(e[q]); l[q] = e[q] - __bfloat162float(h[q]); }
        g_CAh[i] = make_uint4(pkbf16(h[0], h[1]), pkbf16(h[2], h[3]),
                              pkbf16(h[4], h[5]), pkbf16(h[6], h[7]));
        g_CAl[i] = make_uint4(pkbf(l[0], l[1]), pkbf(l[2], l[3]),
                              pkbf(l[4], l[5]), pkbf(l[6], l[7]));
    }
    if (i < 840) { int k = i / 10, j = i % 10; g_w3t[i] = w3[j * 84 + k]; }
}

// ---------------- conv1 (1->6, 5x5) + maxpool2 + relu (R10, FFMA2) -----------
__global__ __launch_bounds__(576) void conv1_kernel(const float* __restrict__ img,
                                                    const float* __restrict__ w,
                                                    const float* __restrict__ b) {
    __shared__ ull   sp[4][812];
    __shared__ ull   swp[150];
    __shared__ float sb[6];
    int t = threadIdx.x;
    size_t n0 = (size_t)blockIdx.x * 8;
    for (int i = t; i < 4 * 784; i += 576) {
        int q = i / 784, j = i % 784;
        int r = j / 28, c = j % 28;
        sp[q][r * 29 + c] = pack2(img[(n0 + 2 * q) * 784 + j],
                                  img[(n0 + 2 * q + 1) * 784 + j]);
    }
    if (t < 150) { float v = w[t]; swp[t] = pack2(v, v); }
    if (t < 6)   sb[t] = b[t];
    __syncthreads();

    int pairIdx = t / 144;
    int pos = t % 144;
    int py = pos / 12, px = pos % 12;
    const ull* si = sp[pairIdx];

    ull acc[6][4];
    #pragma unroll
    for (int ic = 0; ic < 6; ic++)
        #pragma unroll
        for (int q = 0; q < 4; q++) acc[ic][q] = 0ULL;

    #pragma unroll
    for (int ky = 0; ky < 5; ky++) {
        #pragma unroll
        for (int kx = 0; kx < 5; kx++) {
            int base = (2 * py + ky) * 29 + 2 * px + kx;
            ull x00 = si[base],      x01 = si[base + 1];
            ull x10 = si[base + 29], x11 = si[base + 30];
            #pragma unroll
            for (int ic = 0; ic < 6; ic++) {
                ull wq = swp[ic * 25 + ky * 5 + kx];
                acc[ic][0] = ffma2(x00, wq, acc[ic][0]);
                acc[ic][1] = ffma2(x01, wq, acc[ic][1]);
                acc[ic][2] = ffma2(x10, wq, acc[ic][2]);
                acc[ic][3] = ffma2(x11, wq, acc[ic][3]);
            }
        }
    }

    size_t pg = (size_t)blockIdx.x * 4 + pairIdx;
    #pragma unroll
    for (int ic = 0; ic < 6; ic++) {
        float2 a = unpack2(acc[ic][0]), c2 = unpack2(acc[ic][1]);
        float2 d = unpack2(acc[ic][2]), e  = unpack2(acc[ic][3]);
        float bb = sb[ic];
        float oA = fmaxf(fmaxf(fmaxf(a.x, c2.x), fmaxf(d.x, e.x)) + bb, 0.f);
        float oB = fmaxf(fmaxf(fmaxf(a.y, c2.y), fmaxf(d.y, e.y)) + bb, 0.f);
        g_pool1p[pg * 864 + ic * 144 + pos] = pack2(oA, oB);
    }
}

// ---------------- conv2 via implicit-im2col mma.sync -------------------------
// CTA = 8 images (256 threads, 8 warps); warp = 1 image.
// Gather all 8 nt B-fragments into regs, then 3 passes x 8 independent MMAs.
#define CSTRIDE 872
#define CLO     6984            // lo-plane offset (ushort idx) = 8*872 + 8
#define ZIDX    6976u           // zero slot for padded K
__global__ __launch_bounds__(256) void conv2_mma_kernel(const float* __restrict__ b) {
    __shared__ unsigned short sa[2 * CLO];          // hi plane + lo plane
    __shared__ uint4 swf[2][10][32];                // A frags [hi/lo][ks][lane]
    __shared__ float sb[16];
    int t = threadIdx.x, wid = t >> 5, lane = t & 31;
    size_t p0 = (size_t)blockIdx.x * 4;             // 4 pairs = 8 images

    for (int i = t; i < 4 * 864; i += 256) {
        int pr = i / 864, j = i % 864;
        float2 f = unpack2(g_pool1p[p0 * 864 + i]);
        __nv_bfloat16 hA = __float2bfloat16(f.x);
        __nv_bfloat16 hB = __float2bfloat16(f.y);
        float lA = f.x - __bfloat162float(hA);
        float lB = f.y - __bfloat162float(hB);
        int iA = (2 * pr) * CSTRIDE + j;
        int iB = iA + CSTRIDE;
        sa[iA] = __bfloat16_as_ushort(hA);
        sa[iA + CLO] = __bfloat16_as_ushort(__float2bfloat16(lA));
        sa[iB] = __bfloat16_as_ushort(hB);
        sa[iB + CLO] = __bfloat16_as_ushort(__float2bfloat16(lB));
    }
    if (t < 8) { sa[ZIDX + t] = 0; sa[ZIDX + t + CLO] = 0; }
    for (int i = t; i < 640; i += 256)
        ((uint4*)swf)[i] = (i < 320) ? g_CAh[i] : g_CAl[i - 320];
    if (t < 16) sb[t] = b[t];
    __syncthreads();

    int g2 = lane >> 2, tg = lane & 3;
    unsigned pbase = (unsigned)(wid * CSTRIDE);

    float acc[8][4];
    #pragma unroll
    for (int nt = 0; nt < 8; nt++)
        #pragma unroll
        for (int q = 0; q < 4; q++) acc[nt][q] = 0.f;

    #pragma unroll 1
    for (int ks = 0; ks < 10; ks++) {
        uint4 ah = swf[0][ks][lane];
        uint4 al = swf[1][ks][lane];
        int k0 = ks * 16 + tg * 2;
        unsigned ko[4]; bool kv[4];
        #pragma unroll
        for (int j = 0; j < 4; j++) {
            int k = k0 + (j & 1) + (j >> 1) * 8;    // k0, k0+1, k0+8, k0+9
            kv[j] = (k < 150);
            int ic = k / 25, rr = k % 25;
            ko[j] = (unsigned)(ic * 144 + (rr / 5) * 12 + (rr % 5));
        }
        // ---- gather all 8 nt B-fragments first (independent LDS) ----
        uint32_t bh0[8], bh1[8], bl0[8], bl1[8];
        #pragma unroll
        for (int nt = 0; nt < 8; nt++) {
            unsigned base = pbase + (unsigned)(nt * 12 + g2);
            unsigned i0 = kv[0] ? base + ko[0] : ZIDX;
            unsigned i1 = kv[1] ? base + ko[1] : ZIDX;
            unsigned i2 = kv[2] ? base + ko[2] : ZIDX;
            unsigned i3 = kv[3] ? base + ko[3] : ZIDX;
            uint32_t e0 = sa[i0], e1 = sa[i1], e2 = sa[i2], e3 = sa[i3];
            uint32_t f0 = sa[i0 + CLO], f1 = sa[i1 + CLO], f2 = sa[i2 + CLO], f3 = sa[i3 + CLO];
            bh0[nt] = (e1 << 16) | e0; bh1[nt] = (e3 << 16) | e2;
            bl0[nt] = (f1 << 16) | f0; bl1[nt] = (f3 << 16) | f2;
        }
        // ---- 3 passes of 8 independent MMAs (reuse distance 8) ----
        #pragma unroll
        for (int nt = 0; nt < 8; nt++)
            MMA_BF16(acc[nt], ah.x, ah.y, ah.z, ah.w, bh0[nt], bh1[nt]);
        #pragma unroll
        for (int nt = 0; nt < 8; nt++)
            MMA_BF16(acc[nt], ah.x, ah.y, ah.z, ah.w, bl0[nt], bl1[nt]);
        #pragma unroll
        for (int nt = 0; nt < 8; nt++)
            MMA_BF16(acc[nt], al.x, al.y, al.z, al.w, bh0[nt], bh1[nt]);
    }

    // thread holds conv[oc=g2][oy=nt][ox=tg*2,tg*2+1] (c0,c1) and oc=g2+8 (c2,c3)
    size_t img = (size_t)blockIdx.x * 8 + wid;
    float* op = g_pool2f + img * 256;
    float b0 = sb[g2], b1 = sb[g2 + 8];
    #pragma unroll
    for (int py = 0; py < 4; py++) {
        float m0 = fmaxf(fmaxf(acc[2 * py][0], acc[2 * py][1]),
                         fmaxf(acc[2 * py + 1][0], acc[2 * py + 1][1]));
        float m1 = fmaxf(fmaxf(acc[2 * py][2], acc[2 * py][3]),
                         fmaxf(acc[2 * py + 1][2], acc[2 * py + 1][3]));
        op[g2 * 16 + py * 4 + tg]       = fmaxf(m0 + b0, 0.f);
        op[(g2 + 8) * 16 + py * 4 + tg] = fmaxf(m1 + b1, 0.f);
    }
}

// ---------------- fc chain on mma.sync (R12 geometry + pass reorder) ---------
// CTA = 128 images, 256 threads (8 warps); warp w owns rows w*16..w*16+15.
#define SAW 264
#define A_HI 0
#define A_LO 67584
#define SH2  135168
#define SB1  181248
#define SB2  181760
#define SB3  182144
#define SW3  182208
#define S_TOTAL 185600

__global__ __launch_bounds__(256, 1)
void fc_mma_kernel(const float* __restrict__ b1, const float* __restrict__ b2,
                   const float* __restrict__ b3) {
    extern __shared__ __align__(16) char sm[];
    int t = threadIdx.x, wid = t >> 5, lane = t & 31;
    float* sb1 = (float*)(sm + SB1);
    float* sb2 = (float*)(sm + SB2);
    float* sb3 = (float*)(sm + SB3);
    float* sw3 = (float*)(sm + SW3);
    float* sh2 = (float*)(sm + SH2);

    if (t < 120) sb1[t] = b1[t];
    if (t < 84)  sb2[t] = b2[t];
    if (t < 10)  sb3[t] = b3[t];
    for (int i = t; i < 840; i += 256) sw3[i] = g_w3t[i];

    // ---- stage A1: fp32 -> bf16 hi/lo ----
    {
        int r = t >> 1, kh = t & 1;
        size_t img = (size_t)blockIdx.x * 128 + r;
        const float* xp = g_pool2f + img * 256 + kh * 128;
        #pragma unroll 4
        for (int u = 0; u < 64; u++) {
            int k = kh * 128 + 2 * u;
            float x0 = xp[2 * u], x1 = xp[2 * u + 1];
            __nv_bfloat16 h0 = __float2bfloat16(x0), h1 = __float2bfloat16(x1);
            float l0 = x0 - __bfloat162float(h0);
            float l1 = x1 - __bfloat162float(h1);
            *(uint32_t*)(sm + A_HI + ((size_t)r * SAW + k) * 2) = pkbf16(h0, h1);
            *(uint32_t*)(sm + A_LO + ((size_t)r * SAW + k) * 2) = pkbf(l0, l1);
        }
    }
    __syncthreads();

    // ---- fc1 ----
    int r0 = wid * 16;
    int ar = r0 + (lane >> 2);
    float acc[16][4];
    #pragma unroll
    for (int nt = 0; nt < 16; nt++)
        #pragma unroll
        for (int q = 0; q < 4; q++) acc[nt][q] = 0.f;

    #pragma unroll 1
    for (int ks = 0; ks < 16; ks++) {
        int ac = ks * 16 + (lane & 3) * 2;
        uint32_t ah0 = *(uint32_t*)(sm + A_HI + ((size_t)ar * SAW + ac) * 2);
        uint32_t ah1 = *(uint32_t*)(sm + A_HI + ((size_t)(ar + 8) * SAW + ac) * 2);
        uint32_t ah2 = *(uint32_t*)(sm + A_HI + ((size_t)ar * SAW + ac + 8) * 2);
        uint32_t ah3 = *(uint32_t*)(sm + A_HI + ((size_t)(ar + 8) * SAW + ac + 8) * 2);
        uint32_t al0 = *(uint32_t*)(sm + A_LO + ((size_t)ar * SAW + ac) * 2);
        uint32_t al1 = *(uint32_t*)(sm + A_LO + ((size_t)(ar + 8) * SAW + ac) * 2);
        uint32_t al2 = *(uint32_t*)(sm + A_LO + ((size_t)ar * SAW + ac + 8) * 2);
        uint32_t al3 = *(uint32_t*)(sm + A_LO + ((size_t)(ar + 8) * SAW + ac + 8) * 2);
        // pass 1: hi x hi
        #pragma unroll
        for (int nt = 0; nt < 16; nt++) {
            uint2 bh = g_B1fh[ks * 512 + nt * 32 + lane];
            MMA_BF16(acc[nt], ah0, ah1, ah2, ah3, bh.x, bh.y);
        }
        // pass 2: hi x lo
        #pragma unroll
        for (int nt = 0; nt < 16; nt++) {
            uint2 bl = g_B1fl[ks * 512 + nt * 32 + lane];
            MMA_BF16(acc[nt], ah0, ah1, ah2, ah3, bl.x, bl.y);
        }
        // pass 3: lo x hi
        #pragma unroll
        for (int nt = 0; nt < 16; nt++) {
            uint2 bh = g_B1fh[ks * 512 + nt * 32 + lane];
            MMA_BF16(acc[nt], al0, al1, al2, al3, bh.x, bh.y);
        }
    }

    // ---- bias + relu -> A2 fragments in registers ----
    uint32_t a2h[8][4], a2l[8][4];
    #pragma unroll
    for (int k2 = 0; k2 < 8; k2++) {
        #pragma unroll
        for (int e = 0; e < 2; e++) {
            int nt = 2 * k2 + e;
            int j0 = nt * 8 + (lane & 3) * 2;
            float bb0 = (j0 < 120)     ? sb1[j0]     : 0.f;
            float bb1 = (j0 + 1 < 120) ? sb1[j0 + 1] : 0.f;
            float v0 = fmaxf(acc[nt][0] + bb0, 0.f);
            float v1 = fmaxf(acc[nt][1] + bb1, 0.f);
            float v2 = fmaxf(acc[nt][2] + bb0, 0.f);
            float v3 = fmaxf(acc[nt][3] + bb1, 0.f);
            __nv_bfloat16 h0 = __float2bfloat16(v0), h1 = __float2bfloat16(v1);
            __nv_bfloat16 h2 = __float2bfloat16(v2), h3 = __float2bfloat16(v3);
            a2h[k2][0 + 2 * e] = pkbf16(h0, h1);
            a2h[k2][1 + 2 * e] = pkbf16(h2, h3);
            a2l[k2][0 + 2 * e] = pkbf(v0 - __bfloat162float(h0), v1 - __bfloat162float(h1));
            a2l[k2][1 + 2 * e] = pkbf(v2 - __bfloat162float(h2), v3 - __bfloat162float(h3));
        }
    }

    // ---- fc2 (pass-reordered) ----
    float acc2[11][4];
    #pragma unroll
    for (int nt = 0; nt < 11; nt++)
        #pragma unroll
        for (int q = 0; q < 4; q++) acc2[nt][q] = 0.f;
    #pragma unroll 1
    for (int ks = 0; ks < 8; ks++) {
        #pragma unroll
        for (int nt = 0; nt < 11; nt++) {
            uint2 bh = g_B2fh[ks * 352 + nt * 32 + lane];
            MMA_BF16(acc2[nt], a2h[ks][0], a2h[ks][1], a2h[ks][2], a2h[ks][3], bh.x, bh.y);
        }
        #pragma unroll
        for (int nt = 0; nt < 11; nt++) {
            uint2 bl = g_B2fl[ks * 352 + nt * 32 + lane];
            MMA_BF16(acc2[nt], a2h[ks][0], a2h[ks][1], a2h[ks][2], a2h[ks][3], bl.x, bl.y);
        }
        #pragma unroll
        for (int nt = 0; nt < 11; nt++) {
            uint2 bh = g_B2fh[ks * 352 + nt * 32 + lane];
            MMA_BF16(acc2[nt], a2l[ks][0], a2l[ks][1], a2l[ks][2], a2l[ks][3], bh.x, bh.y);
        }
    }

    // ---- bias + relu -> h2 fp32 smem ----
    {
        int rr = r0 + (lane >> 2);
        #pragma unroll
        for (int nt = 0; nt < 11; nt++) {
            int j0 = nt * 8 + (lane & 3) * 2;
            float bb0 = (j0 < 84)     ? sb2[j0]     : 0.f;
            float bb1 = (j0 + 1 < 84) ? sb2[j0 + 1] : 0.f;
            *(float2*)(sh2 + (size_t)rr * 90 + j0) =
                make_float2(fmaxf(acc2[nt][0] + bb0, 0.f), fmaxf(acc2[nt][1] + bb1, 0.f));
            *(float2*)(sh2 + (size_t)(rr + 8) * 90 + j0) =
                make_float2(fmaxf(acc2[nt][2] + bb0, 0.f), fmaxf(acc2[nt][3] + bb1, 0.f));
        }
    }
    __syncthreads();

    // ---- fc3 + log-softmax ----
    if (t < 128) {
        const float* hp = sh2 + (size_t)t * 90;
        float o[10];
        #pragma unroll
        for (int j = 0; j < 10; j++) o[j] = sb3[j];
        #pragma unroll 4
        for (int k = 0; k < 84; k++) {
            float hv = hp[k];
            #pragma unroll
            for (int j = 0; j < 10; j++) o[j] = fmaf(hv, sw3[k * 10 + j], o[j]);
        }
        float m = -1e30f;
        #pragma unroll
        for (int j = 0; j < 10; j++) m = fmaxf(m, o[j]);
        float s = 0.f;
        #pragma unroll
        for (int j = 0; j < 10; j++) s += __expf(o[j] - m);
        float lse = m + __logf(s);
        float* op = g_logp + ((size_t)blockIdx.x * 128 + t) * 10;
        #pragma unroll
        for (int j = 0; j < 10; j++) op[j] = o[j] - lse;
    }
}

// ---------------- probabilistic circuit (R10) ----------------
__global__ __launch_bounds__(256) void circuit_kernel(float* __restrict__ out) {
    __shared__ float lp[40];
    __shared__ float e1[100];
    __shared__ float e2[100];
    int bI = blockIdx.x;
    int t = threadIdx.x;
    if (t < 40) lp[t] = g_logp[(size_t)bI * 40 + t];
    __syncthreads();
    if (t < 100) {
        e1[t] = __expf(lp[0 + t / 10] + lp[10 + t % 10]);
    } else if (t < 200) {
        int k = t - 100;
        e2[k] = __expf(lp[20 + k / 10] + lp[30 + k % 10]);
    }
    __syncthreads();
    if (t < SUMS) {
        int lo = t > 99 ? t - 99 : 0;
        int hi = t < 99 ? t : 99;
        float s = 0.f;
        for (int i = lo; i <= hi; i++) s = fmaf(e1[i], e2[t - i], s);
        out[(size_t)bI * SUMS + t] = __logf(s);
    }
}

// ---------------- launch ----------------
extern "C" void kernel_launch(void* const* d_in, const int* in_sizes, int n_in,
                              void* d_out, int out_size) {
    const float* images = (const float*)d_in[0];
    const float* c1w    = (const float*)d_in[1];
    const float* c1b    = (const float*)d_in[2];
    const float* c2w    = (const float*)d_in[3];
    const float* c2b    = (const float*)d_in[4];
    const float* f1w    = (const float*)d_in[5];
    const float* f1b    = (const float*)d_in[6];
    const float* f2w    = (const float*)d_in[7];
    const float* f2b    = (const float*)d_in[8];
    const float* f3w    = (const float*)d_in[9];
    const float* f3b    = (const float*)d_in[10];
    float* out = (float*)d_out;

    cudaFuncSetAttribute(fc_mma_kernel, cudaFuncAttributeMaxDynamicSharedMemorySize, S_TOTAL);

    prep_kernel<<<44, 256>>>(c2w, f1w, f2w, f3w);
    conv1_kernel<<<NPAIR / 4, 576>>>(images, c1w, c1b);
    conv2_mma_kernel<<<N_IMG / 8, 256>>>(c2b);
    fc_mma_kernel<<<N_IMG / 128, 256, S_TOTAL>>>(f1b, f2b, f3b);
    circuit_kernel<<<NBATCH, 256>>>(out);
}